// round 7
// baseline (speedup 1.0000x reference)
#include <cuda_runtime.h>
#include <math.h>

#define MAXN 50000
#define MAXETOT 850000   // E + N self loops

// ---------------- scratch (static __device__, no allocation) ----------------
__device__ int   g_deg[MAXN];
__device__ int   g_off[MAXN + 1];
__device__ int   g_cur[MAXN];
__device__ int   g_srcl[MAXETOT];
__device__ float g_dinv[MAXN];

__device__ float g_h1 [MAXN * 256];   // layer1 linear output  [N,8,32]
__device__ float g_as1[MAXN * 8];
__device__ float g_ad1[MAXN * 8];
__device__ float g_m1 [MAXN * 8];     // per-(node,head) softmax max
__device__ float g_i1 [MAXN * 8];     // per-(node,head) 1/sum
__device__ float g_h1e[MAXN * 256];   // elu(gat1 out)
__device__ float g_h2 [MAXN * 16];    // layer2 linear output
__device__ float g_as2[MAXN];
__device__ float g_ad2[MAXN];
__device__ float g_h3 [MAXN * 16];    // elu(gat2 out) @ W3 (GCN is linear -> fold W3 early)

__device__ __forceinline__ float lrelu(float x) { return x > 0.f ? x : 0.2f * x; }
__device__ __forceinline__ float elu_f(float x) { return x > 0.f ? x : expm1f(x); }

// FMA-pipe exp (avoids MUFU throughput wall). |err| ~ 2e-6 rel.
__device__ __forceinline__ float fexp(float x) {
    x = fmaxf(x, -80.f);
    float y = x * 1.44269504f;
    float r = rintf(y);
    float f = y - r;
    float p =             1.3333558e-3f;
    p = fmaf(p, f, 9.6181291e-3f);
    p = fmaf(p, f, 5.5504109e-2f);
    p = fmaf(p, f, 2.4022651e-1f);
    p = fmaf(p, f, 6.9314718e-1f);
    p = fmaf(p, f, 1.0f);
    int e = (int)r;
    float s = __int_as_float((e + 127) << 23);
    return p * s;
}

// ---------------- CSR build ----------------
__global__ void k_zero_deg(int N) {
    int i = blockIdx.x * blockDim.x + threadIdx.x;
    if (i < N) g_deg[i] = 0;
}

__global__ void k_hist(const int* __restrict__ ei, int E, int N) {
    int e = blockIdx.x * blockDim.x + threadIdx.x;
    int Etot = E + N;
    if (e >= Etot) return;
    int d = (e < E) ? ei[E + e] : (e - E);
    atomicAdd(&g_deg[d], 1);
}

__global__ void k_scan(int N, int Etot) {
    __shared__ int sums[1024];
    int t = threadIdx.x;
    int chunk = (N + 1023) >> 10;
    int b = t * chunk;
    int e = min(b + chunk, N);
    int s = 0;
    for (int i = b; i < e; i++) s += g_deg[i];
    sums[t] = s;
    __syncthreads();
    for (int o = 1; o < 1024; o <<= 1) {
        int v = (t >= o) ? sums[t - o] : 0;
        __syncthreads();
        sums[t] += v;
        __syncthreads();
    }
    int base = (t > 0) ? sums[t - 1] : 0;
    for (int i = b; i < e; i++) {
        int d = g_deg[i];
        g_off[i] = base;
        g_cur[i] = base;
        g_dinv[i] = rsqrtf((float)d);
        base += d;
    }
    if (t == 0) g_off[N] = Etot;
}

__global__ void k_fill(const int* __restrict__ ei, int E, int N) {
    int e = blockIdx.x * blockDim.x + threadIdx.x;
    int Etot = E + N;
    if (e >= Etot) return;
    int s, d;
    if (e < E) { s = ei[e]; d = ei[E + e]; }
    else       { s = e - E; d = e - E; }
    int pos = atomicAdd(&g_cur[d], 1);
    g_srcl[pos] = s;
}

// ---------------- GEMM1: h1 = x @ W1, 128x128 tile, fused alpha epilogue -----
__global__ void k_gemm1(const float* __restrict__ A, const float* __restrict__ B,
                        const float* __restrict__ a_src1, const float* __restrict__ a_dst1,
                        int M) {
    __shared__ float As[16][128];
    __shared__ float Bs[16][128];
    int tid = threadIdx.x;
    int tx = tid & 15, ty = tid >> 4;
    int rowBase = blockIdx.y * 128, colBase = blockIdx.x * 128;
    float acc[8][8] = {};
    for (int k0 = 0; k0 < 128; k0 += 16) {
#pragma unroll
        for (int p = 0; p < 2; p++) {
            int f = tid + p * 256;
            int m = f & 127, kq = f >> 7;         // kq 0..3
            int gr = rowBase + m;
            float4 v = make_float4(0.f, 0.f, 0.f, 0.f);
            if (gr < M) v = *(const float4*)(A + gr * 128 + k0 + kq * 4);
            As[kq * 4 + 0][m] = v.x; As[kq * 4 + 1][m] = v.y;
            As[kq * 4 + 2][m] = v.z; As[kq * 4 + 3][m] = v.w;
        }
#pragma unroll
        for (int p = 0; p < 2; p++) {
            int f = tid + p * 256;
            int kk = f >> 5, n4 = f & 31;
            *(float4*)&Bs[kk][n4 * 4] = *(const float4*)(B + (k0 + kk) * 256 + colBase + n4 * 4);
        }
        __syncthreads();
#pragma unroll
        for (int kk = 0; kk < 16; kk++) {
            float a[8], b[8];
            *(float4*)&a[0] = *(float4*)&As[kk][ty * 8];
            *(float4*)&a[4] = *(float4*)&As[kk][ty * 8 + 4];
            *(float4*)&b[0] = *(float4*)&Bs[kk][tx * 8];
            *(float4*)&b[4] = *(float4*)&Bs[kk][tx * 8 + 4];
#pragma unroll
            for (int i = 0; i < 8; i++)
#pragma unroll
                for (int j = 0; j < 8; j++) acc[i][j] = fmaf(a[i], b[j], acc[i][j]);
        }
        __syncthreads();
    }
    // epilogue: write h1 + fused attention logits (head = 32 cols = tx quad)
    int head = (colBase >> 5) + (tx >> 2);
    int cbase = (tx & 3) * 8;
    float asv[8], adv[8];
#pragma unroll
    for (int j = 0; j < 8; j++) {
        asv[j] = a_src1[head * 32 + cbase + j];
        adv[j] = a_dst1[head * 32 + cbase + j];
    }
#pragma unroll
    for (int i = 0; i < 8; i++) {
        int gr = rowBase + ty * 8 + i;
        float ps = 0.f, pd = 0.f;
#pragma unroll
        for (int j = 0; j < 8; j++) {
            ps = fmaf(acc[i][j], asv[j], ps);
            pd = fmaf(acc[i][j], adv[j], pd);
        }
        ps += __shfl_xor_sync(0xffffffffu, ps, 1);
        ps += __shfl_xor_sync(0xffffffffu, ps, 2);
        pd += __shfl_xor_sync(0xffffffffu, pd, 1);
        pd += __shfl_xor_sync(0xffffffffu, pd, 2);
        if (gr < M) {
            *(float4*)(g_h1 + gr * 256 + colBase + tx * 8)     = *(float4*)&acc[i][0];
            *(float4*)(g_h1 + gr * 256 + colBase + tx * 8 + 4) = *(float4*)&acc[i][4];
            if ((tx & 3) == 0) {
                g_as1[gr * 8 + head] = ps;
                g_ad1[gr * 8 + head] = pd;
            }
        }
    }
}

// ---------------- layer1 softmax stats (warp per dst node) ----------------
__global__ void k_stats1(int N) {
    int w = (blockIdx.x * blockDim.x + threadIdx.x) >> 5;
    int lane = threadIdx.x & 31;
    if (w >= N) return;
    int beg = g_off[w], end = g_off[w + 1];
    int h8 = lane & 7;
    float adA = g_ad1[w * 8 + h8];
    float m = -1e30f, ssum = 0.f;
    for (int e = beg + (lane >> 3); e < end; e += 4) {
        int s = g_srcl[e];
        float l = lrelu(g_as1[s * 8 + h8] + adA);
        float nm = fmaxf(m, l);
        ssum = ssum * fexp(m - nm) + fexp(l - nm);
        m = nm;
    }
#pragma unroll
    for (int o = 8; o < 32; o <<= 1) {
        float mo = __shfl_xor_sync(0xffffffffu, m, o);
        float so = __shfl_xor_sync(0xffffffffu, ssum, o);
        float nm = fmaxf(m, mo);
        ssum = ssum * fexp(m - nm) + so * fexp(mo - nm);
        m = nm;
    }
    if (lane < 8) {
        g_m1[w * 8 + lane] = m;
        g_i1[w * 8 + lane] = 1.f / ssum;
    }
}

// ---------------- layer1 aggregation: 2 warps / node, 128 cols each ----------
__global__ void k_edge1b(const float* __restrict__ b1, int N) {
    int w = (blockIdx.x * blockDim.x + threadIdx.x) >> 5;
    int lane = threadIdx.x & 31;
    int node = w >> 1, half = w & 1;
    if (node >= N) return;
    int colb = half * 128 + lane * 4;
    int h = colb >> 5;
    float adB = g_ad1[node * 8 + h];
    float mb  = g_m1 [node * 8 + h];
    float inv = g_i1 [node * 8 + h];
    int beg = g_off[node], end = g_off[node + 1];
    float ax = 0.f, ay = 0.f, az = 0.f, aw = 0.f;
    int e = beg;
    for (; e + 2 <= end; e += 2) {
        int s0 = g_srcl[e], s1 = g_srcl[e + 1];
        float l0 = lrelu(g_as1[s0 * 8 + h] + adB);
        float l1 = lrelu(g_as1[s1 * 8 + h] + adB);
        float w0 = fexp(l0 - mb) * inv;
        float w1 = fexp(l1 - mb) * inv;
        float4 v0 = *(const float4*)(g_h1 + s0 * 256 + colb);
        float4 v1 = *(const float4*)(g_h1 + s1 * 256 + colb);
        ax += w0 * v0.x + w1 * v1.x;
        ay += w0 * v0.y + w1 * v1.y;
        az += w0 * v0.z + w1 * v1.z;
        aw += w0 * v0.w + w1 * v1.w;
    }
    if (e < end) {
        int s0 = g_srcl[e];
        float l0 = lrelu(g_as1[s0 * 8 + h] + adB);
        float w0 = fexp(l0 - mb) * inv;
        float4 v0 = *(const float4*)(g_h1 + s0 * 256 + colb);
        ax += w0 * v0.x; ay += w0 * v0.y; az += w0 * v0.z; aw += w0 * v0.w;
    }
    float4 bb = *(const float4*)(b1 + colb);
    float4 o;
    o.x = elu_f(ax + bb.x); o.y = elu_f(ay + bb.y);
    o.z = elu_f(az + bb.z); o.w = elu_f(aw + bb.w);
    *(float4*)(g_h1e + node * 256 + colb) = o;
}

// ---------------- mm2: h2 = h1e @ W2 (+ alpha2) -------------------------------
// 128 threads, 8 nodes/block; thread = (node, j4, ksplit); float4 W2 rows.
__global__ void k_mm2(const float* __restrict__ W2,
                      const float* __restrict__ a_src2, const float* __restrict__ a_dst2,
                      int N) {
    __shared__ float xs[8][264];
    __shared__ float W2s[256 * 16];
    int tid = threadIdx.x;
    int nb = blockIdx.x * 8;
    for (int f = tid; f < 1024; f += 128)
        ((float4*)W2s)[f] = ((const float4*)W2)[f];
    for (int f = tid; f < 512; f += 128) {
        int node = f >> 6, c4 = f & 63;
        int gn = nb + node;
        float4 v = (gn < N) ? ((const float4*)g_h1e)[gn * 64 + c4]
                            : make_float4(0.f, 0.f, 0.f, 0.f);
        *(float4*)&xs[node][c4 * 4] = v;
    }
    __syncthreads();
    int node = tid >> 4;
    int j4 = (tid >> 2) & 3;
    int ks = tid & 3;
    float4 acc = make_float4(0.f, 0.f, 0.f, 0.f);
#pragma unroll 8
    for (int kk = 0; kk < 64; kk++) {
        int k = kk * 4 + ks;
        float xv = xs[node][k];
        float4 wv = *(const float4*)&W2s[k * 16 + j4 * 4];
        acc.x = fmaf(xv, wv.x, acc.x);
        acc.y = fmaf(xv, wv.y, acc.y);
        acc.z = fmaf(xv, wv.z, acc.z);
        acc.w = fmaf(xv, wv.w, acc.w);
    }
#pragma unroll
    for (int o = 1; o < 4; o <<= 1) {
        acc.x += __shfl_xor_sync(0xffffffffu, acc.x, o);
        acc.y += __shfl_xor_sync(0xffffffffu, acc.y, o);
        acc.z += __shfl_xor_sync(0xffffffffu, acc.z, o);
        acc.w += __shfl_xor_sync(0xffffffffu, acc.w, o);
    }
    int gn = nb + node;
    if (ks == 0 && gn < N)
        *(float4*)&g_h2[gn * 16 + j4 * 4] = acc;
    // alpha2
    float4 av = *(const float4*)&a_src2[j4 * 4];
    float4 dv = *(const float4*)&a_dst2[j4 * 4];
    float pa = acc.x * av.x + acc.y * av.y + acc.z * av.z + acc.w * av.w;
    float pd = acc.x * dv.x + acc.y * dv.y + acc.z * dv.z + acc.w * dv.w;
#pragma unroll
    for (int o = 4; o < 16; o <<= 1) {
        pa += __shfl_xor_sync(0xffffffffu, pa, o);
        pd += __shfl_xor_sync(0xffffffffu, pd, o);
    }
    if (ks == 0 && j4 == 0 && gn < N) {
        g_as2[gn] = pa;
        g_ad2[gn] = pd;
    }
}

// ---------------- GAT layer 2 + elu + fold @W3: 2 nodes per warp --------------
__global__ void k_edge2(const float* __restrict__ b2, const float* __restrict__ W3, int N) {
    int gw = (blockIdx.x * blockDim.x + threadIdx.x) >> 5;
    int lane = threadIdx.x & 31;
    if (gw * 2 >= N) return;
    int sub = lane >> 4, l16 = lane & 15;
    int node = gw * 2 + sub;
    int nd = min(node, N - 1);           // clamp; writes guarded
    int beg = g_off[nd], end = g_off[nd + 1];
    float adv = g_ad2[nd];

    // pass A: softmax stats over 16-lane group
    float m = -1e30f, ssum = 0.f;
    for (int e = beg + l16; e < end; e += 16) {
        int s = g_srcl[e];
        float l = lrelu(g_as2[s] + adv);
        float nm = fmaxf(m, l);
        ssum = ssum * fexp(m - nm) + fexp(l - nm);
        m = nm;
    }
#pragma unroll
    for (int o = 1; o < 16; o <<= 1) {
        float mo = __shfl_xor_sync(0xffffffffu, m, o);
        float so = __shfl_xor_sync(0xffffffffu, ssum, o);
        float nm = fmaxf(m, mo);
        ssum = ssum * fexp(m - nm) + so * fexp(mo - nm);
        m = nm;
    }
    float inv = 1.f / ssum;

    // pass B
    float acc = 0.f;
    int e = beg;
    for (; e + 2 <= end; e += 2) {
        int s0 = g_srcl[e], s1 = g_srcl[e + 1];
        float l0 = lrelu(g_as2[s0] + adv);
        float l1 = lrelu(g_as2[s1] + adv);
        float w0 = fexp(l0 - m) * inv;
        float w1 = fexp(l1 - m) * inv;
        acc += w0 * g_h2[s0 * 16 + l16] + w1 * g_h2[s1 * 16 + l16];
    }
    if (e < end) {
        int s0 = g_srcl[e];
        float l0 = lrelu(g_as2[s0] + adv);
        acc += fexp(l0 - m) * inv * g_h2[s0 * 16 + l16];
    }
    float h2e = elu_f(acc + b2[l16]);
    // fold GCN weight: h3 = h2e @ W3 (16x16) via shuffles within 16-group
    float h3 = 0.f;
#pragma unroll
    for (int k = 0; k < 16; k++) {
        float v = __shfl_sync(0xffffffffu, h2e, sub * 16 + k);
        h3 = fmaf(v, W3[k * 16 + l16], h3);
    }
    if (node < N) g_h3[node * 16 + l16] = h3;
}

// ---------------- GCN aggregation: 2 nodes per warp ----------------
__global__ void k_gcn(const float* __restrict__ b3, float* __restrict__ out, int N) {
    int gw = (blockIdx.x * blockDim.x + threadIdx.x) >> 5;
    int lane = threadIdx.x & 31;
    if (gw * 2 >= N) return;
    int sub = lane >> 4, l16 = lane & 15;
    int node = gw * 2 + sub;
    int nd = min(node, N - 1);
    int beg = g_off[nd], end = g_off[nd + 1];
    float dv = g_dinv[nd];
    float acc = 0.f;
    int e = beg;
    for (; e + 2 <= end; e += 2) {
        int s0 = g_srcl[e], s1 = g_srcl[e + 1];
        acc += g_dinv[s0] * dv * g_h3[s0 * 16 + l16]
             + g_dinv[s1] * dv * g_h3[s1 * 16 + l16];
    }
    if (e < end) {
        int s0 = g_srcl[e];
        acc += g_dinv[s0] * dv * g_h3[s0 * 16 + l16];
    }
    if (node < N) out[node * 16 + l16] = acc + b3[l16];
}

// ---------------- host ----------------
extern "C" void kernel_launch(void* const* d_in, const int* in_sizes, int n_in,
                              void* d_out, int out_size) {
    const float* x   = (const float*)d_in[0];
    const int*   ei  = (const int*)  d_in[1];
    const float* W1  = (const float*)d_in[2];
    const float* as1 = (const float*)d_in[3];
    const float* ad1 = (const float*)d_in[4];
    const float* b1  = (const float*)d_in[5];
    const float* W2  = (const float*)d_in[6];
    const float* as2 = (const float*)d_in[7];
    const float* ad2 = (const float*)d_in[8];
    const float* b2  = (const float*)d_in[9];
    const float* W3  = (const float*)d_in[10];
    const float* b3  = (const float*)d_in[11];
    float* out = (float*)d_out;

    int N = in_sizes[0] / 128;
    int E = in_sizes[1] / 2;
    int Etot = E + N;

    int nB = (N + 255) / 256;
    int eB = (Etot + 255) / 256;

    k_zero_deg<<<nB, 256>>>(N);
    k_hist<<<eB, 256>>>(ei, E, N);
    k_scan<<<1, 1024>>>(N, Etot);
    k_fill<<<eB, 256>>>(ei, E, N);

    dim3 g1(2, (N + 127) / 128);
    k_gemm1<<<g1, 256>>>(x, W1, as1, ad1, N);

    k_stats1<<<(N + 7) / 8, 256>>>(N);
    k_edge1b<<<(N + 3) / 4, 256>>>(b1, N);
    k_mm2<<<(N + 7) / 8, 128>>>(W2, as2, ad2, N);
    k_edge2<<<(N + 15) / 16, 256>>>(b2, W3, N);
    k_gcn<<<(N + 15) / 16, 256>>>(b3, out, N);
}